// round 15
// baseline (speedup 1.0000x reference)
#include <cuda_runtime.h>
#include <cuda_bf16.h>
#include <cuda_fp16.h>
#include <cstdint>
#include <math.h>

#define LL   8
#define NN   16384
#define KC   16
#define DD   256
#define D4   (4*DD)
#define D3   (3*DD)
#define NTOT (LL*NN)            // 131072

#define SW64(o) ((o) ^ (((o) >> 3) & 0x30))
#define TILE32 8192             // one 128x32 bf16 tile (64B rows, SW64)
#define STG 32768u              // stage: Ahi|Alo|Bhi|Blo x 8KB

__device__ __forceinline__ uint32_t smem_u32(const void* p) {
    uint32_t a;
    asm("{ .reg .u64 t; cvta.to.shared.u64 t, %1; cvt.u32.u64 %0, t; }" : "=r"(a) : "l"(p));
    return a;
}
__device__ __forceinline__ void ldsm_x4(uint32_t& r0, uint32_t& r1, uint32_t& r2,
                                        uint32_t& r3, uint32_t addr) {
    asm volatile("ldmatrix.sync.aligned.m8n8.x4.shared.b16 {%0,%1,%2,%3}, [%4];"
                 : "=r"(r0), "=r"(r1), "=r"(r2), "=r"(r3) : "r"(addr));
}
__device__ __forceinline__ void mma16816(float* c, const uint32_t* a, const uint32_t* b) {
    asm volatile("mma.sync.aligned.m16n8k16.row.col.f32.bf16.bf16.f32 "
                 "{%0,%1,%2,%3}, {%4,%5,%6,%7}, {%8,%9}, {%0,%1,%2,%3};"
                 : "+f"(c[0]), "+f"(c[1]), "+f"(c[2]), "+f"(c[3])
                 : "r"(a[0]), "r"(a[1]), "r"(a[2]), "r"(a[3]), "r"(b[0]), "r"(b[1]));
}
__device__ __forceinline__ float sigmoid_fast(float z) {
    float t;
    asm("tanh.approx.f32 %0, %1;" : "=f"(t) : "f"(0.5f * z));
    return fmaf(0.5f, t, 0.5f);
}
__device__ __forceinline__ float sigmoid_hw(float z) {
    return 1.f / (1.f + __expf(-z));
}
__device__ __forceinline__ float tanh_hw(float z) {
    return 1.f - 2.f / (__expf(2.f * z) + 1.f);
}
#define CP_ASYNC16(dst, src) \
    asm volatile("cp.async.cg.shared.global [%0], [%1], 16;" :: "r"(dst), "l"(src))
#define CP_COMMIT asm volatile("cp.async.commit_group;" ::: "memory")
#define CP_WAIT2  asm volatile("cp.async.wait_group 2;" ::: "memory")
#define CP_WAIT1  asm volatile("cp.async.wait_group 1;" ::: "memory")
#define CP_WAIT0  asm volatile("cp.async.wait_group 0;" ::: "memory")

// ---------------- scratch (device globals) ---------------------------------
__device__ __half g_Wf16[NTOT * DD];   // fp16 (pre-activation, non-recurrent)
__device__ __half g_Hu16[NN * DD];     // fp16 (pre-activation, non-recurrent)
__device__ float  g_f   [NN * DD];
__device__ float  g_iuo [NN * D3];
__device__ __align__(1024) unsigned char g_Axhi[NTOT/128 * 8 * TILE32];
__device__ __align__(1024) unsigned char g_Axlo[NTOT/128 * 8 * TILE32];
__device__ __align__(1024) unsigned char g_Ahshi[NN/128 * 8 * TILE32];
__device__ __align__(1024) unsigned char g_Ahslo[NN/128 * 8 * TILE32];
__device__ __align__(1024) unsigned char g_Ahhi [NN/128 * 8 * TILE32];
__device__ __align__(1024) unsigned char g_Ahlo [NN/128 * 8 * TILE32];
// B tiles: Wf: 0..15 (2nb x 8kc) | U_f: 16..31 | B_ext: 32..127 (6nb x 16kc)
__device__ __align__(1024) unsigned char g_Bhi[128 * TILE32];
__device__ __align__(1024) unsigned char g_Blo[128 * TILE32];

// ---------------- weight prep ----------------------------------------------
__device__ __forceinline__ void put_b(unsigned tile, int n_loc, int k_loc, float v) {
    __nv_bfloat16 hi = __float2bfloat16(v);
    __nv_bfloat16 lo = __float2bfloat16(v - __bfloat162float(hi));
    unsigned off = tile * TILE32 + SW64((unsigned)(n_loc * 64 + k_loc * 2));
    *(__nv_bfloat16*)(g_Bhi + off) = hi;
    *(__nv_bfloat16*)(g_Blo + off) = lo;
}
__global__ __launch_bounds__(256)
void prep_small(const float* __restrict__ W_w, const float* __restrict__ U_f)
{
    int idx = blockIdx.x * blockDim.x + threadIdx.x;
    int n = idx & 255, k = idx >> 8;
    put_b( 0 + (n >> 7) * 8 + (k >> 5), n & 127, k & 31, W_w[k * 1024 + n]);
    put_b(16 + (n >> 7) * 8 + (k >> 5), n & 127, k & 31, U_f[k * 256 + n]);
}
__global__ __launch_bounds__(256)
void prep_ext(const float* __restrict__ W_w, const float* __restrict__ U_iuo)
{
    int idx = blockIdx.x * blockDim.x + threadIdx.x;
    if (idx >= 512 * 768) return;
    int n = idx % 768, k = idx / 768;
    float v = (k < 256) ? U_iuo[k * 768 + n] : W_w[(k - 256) * 1024 + 256 + n];
    put_b(32 + (n >> 7) * 16 + (k >> 5), n & 127, k & 31, v);
}

// ---------------- x -> bf16 hi/lo tiles -------------------------------------
__global__ __launch_bounds__(256)
void xconv_kernel(const float* __restrict__ x)
{
    int t = blockIdx.x * blockDim.x + threadIdx.x;
    int n = t >> 6, c4 = t & 63;
    float4 v = *(const float4*)&x[(size_t)t * 4];
    __nv_bfloat162 h0, h1, l0, l1;
    h0.x = __float2bfloat16(v.x); h0.y = __float2bfloat16(v.y);
    h1.x = __float2bfloat16(v.z); h1.y = __float2bfloat16(v.w);
    l0.x = __float2bfloat16(v.x - __bfloat162float(h0.x));
    l0.y = __float2bfloat16(v.y - __bfloat162float(h0.y));
    l1.x = __float2bfloat16(v.z - __bfloat162float(h1.x));
    l1.y = __float2bfloat16(v.w - __bfloat162float(h1.y));
    size_t tile = (size_t)(n >> 7) * 8 + (c4 >> 3);
    unsigned off = SW64((unsigned)((n & 127) * 64 + (c4 & 7) * 8));
    uint2 hh, ll;
    hh.x = *(uint32_t*)&h0; hh.y = *(uint32_t*)&h1;
    ll.x = *(uint32_t*)&l0; ll.y = *(uint32_t*)&l1;
    *(uint2*)(g_Axhi + tile * TILE32 + off) = hh;
    *(uint2*)(g_Axlo + tile * TILE32 + off) = ll;
}

// ---------------- 256-thread HMMA GEMM, 128x128 tile, 3-stage --------------
__global__ __launch_bounds__(256, 2)
void gemm_mma(const unsigned char* __restrict__ A0h, const unsigned char* __restrict__ A0l,
              const unsigned char* __restrict__ A1h, const unsigned char* __restrict__ A1l,
              int kchunks, int btile_base,
              const float* __restrict__ bias,
              float* __restrict__ C, __half* __restrict__ C16, int Nc)
{
    extern __shared__ char smem[];
    const uint32_t sb = smem_u32(smem);
    const int tid = threadIdx.x, wid = tid >> 5, lane = tid & 31;
    const int wm = wid & 3, wn = wid >> 2;
    const int mb = blockIdx.y, bn = blockIdx.x * 128;

    float acc[2][8][4];
#pragma unroll
    for (int i = 0; i < 2; i++)
#pragma unroll
        for (int j = 0; j < 8; j++)
#pragma unroll
            for (int q = 0; q < 4; q++) acc[i][j][q] = 0.f;

    const int a_row16 = (lane & 7) + ((lane >> 3) & 1) * 8;
    const int a_kb    = (lane >> 4) * 16;
    const int b_row16 = (lane & 7) + ((lane >> 4) << 3);
    const int b_kb    = ((lane >> 3) & 1) * 16;

    uint32_t aRow[2], aXor[2], bRow[4], bXor[4];
#pragma unroll
    for (int mt = 0; mt < 2; mt++) {
        uint32_t r = (uint32_t)(wm * 32 + mt * 16 + a_row16);
        aRow[mt] = r * 64u; aXor[mt] = (r & 6) * 8u;
    }
#pragma unroll
    for (int np = 0; np < 4; np++) {
        uint32_t r = (uint32_t)(wn * 64 + np * 16 + b_row16);
        bRow[np] = 16384u + r * 64u; bXor[np] = (r & 6) * 8u;
    }

    auto load_stage = [&](int stg, int kc) {
        const unsigned char *ah, *al;
        int kcl;
        if (kc < 8) { ah = A0h; al = A0l; kcl = kc; }
        else        { ah = A1h; al = A1l; kcl = kc - 8; }
        size_t at = ((size_t)mb * 8 + kcl) * TILE32;
        size_t bt = (size_t)(btile_base + blockIdx.x * kchunks + kc) * TILE32;
        const unsigned char* srcs[4] = { ah + at, al + at, g_Bhi + bt, g_Blo + bt };
        uint32_t base = sb + (uint32_t)stg * STG;
#pragma unroll
        for (int j = 0; j < 4; j++) {
            uint32_t d = base + j * TILE32 + tid * 16;
            const unsigned char* s = srcs[j] + tid * 16;
            CP_ASYNC16(d, s);
            CP_ASYNC16(d + 4096, s + 4096);
        }
        CP_COMMIT;
    };

    load_stage(0, 0);
    load_stage(1, 1);
    load_stage(2, 2);

    int stg_i = 0;
    for (int kc = 0; kc < kchunks; kc++) {
        if      (kc + 2 < kchunks) CP_WAIT2;
        else if (kc + 1 < kchunks) CP_WAIT1;
        else                       CP_WAIT0;
        __syncthreads();

        const uint32_t stg = sb + (uint32_t)stg_i * STG;
#pragma unroll
        for (int ks = 0; ks < 2; ks++) {
            const uint32_t ka = (uint32_t)(ks * 32 + a_kb);
            const uint32_t kb = (uint32_t)(ks * 32 + b_kb);
            uint32_t av[2][4], bv[4][4];
            // pass 1: A-hi x B-hi
#pragma unroll
            for (int mt = 0; mt < 2; mt++)
                ldsm_x4(av[mt][0], av[mt][1], av[mt][2], av[mt][3],
                        stg + aRow[mt] + (ka ^ aXor[mt]));
#pragma unroll
            for (int np = 0; np < 4; np++)
                ldsm_x4(bv[np][0], bv[np][1], bv[np][2], bv[np][3],
                        stg + bRow[np] + (kb ^ bXor[np]));
#pragma unroll
            for (int mt = 0; mt < 2; mt++)
#pragma unroll
                for (int nt = 0; nt < 8; nt++)
                    mma16816(acc[mt][nt], av[mt], &bv[nt >> 1][(nt & 1) * 2]);
            // pass 2: A-lo x B-hi (reuse B fragments)
#pragma unroll
            for (int mt = 0; mt < 2; mt++)
                ldsm_x4(av[mt][0], av[mt][1], av[mt][2], av[mt][3],
                        stg + TILE32 + aRow[mt] + (ka ^ aXor[mt]));
#pragma unroll
            for (int mt = 0; mt < 2; mt++)
#pragma unroll
                for (int nt = 0; nt < 8; nt++)
                    mma16816(acc[mt][nt], av[mt], &bv[nt >> 1][(nt & 1) * 2]);
            // pass 3: A-hi x B-lo
#pragma unroll
            for (int mt = 0; mt < 2; mt++)
                ldsm_x4(av[mt][0], av[mt][1], av[mt][2], av[mt][3],
                        stg + aRow[mt] + (ka ^ aXor[mt]));
#pragma unroll
            for (int np = 0; np < 4; np++)
                ldsm_x4(bv[np][0], bv[np][1], bv[np][2], bv[np][3],
                        stg + TILE32 + bRow[np] + (kb ^ bXor[np]));
#pragma unroll
            for (int mt = 0; mt < 2; mt++)
#pragma unroll
                for (int nt = 0; nt < 8; nt++)
                    mma16816(acc[mt][nt], av[mt], &bv[nt >> 1][(nt & 1) * 2]);
        }
        __syncthreads();
        if (kc + 3 < kchunks) load_stage(stg_i, kc + 3);
        stg_i = (stg_i == 2) ? 0 : stg_i + 1;
    }

    // epilogue
    const int r0 = lane >> 2, c0 = (lane & 3) * 2;
    const int bm = mb * 128;
#pragma unroll
    for (int mt = 0; mt < 2; mt++) {
#pragma unroll
        for (int nt = 0; nt < 8; nt++) {
            int row = bm + wm * 32 + mt * 16 + r0;
            int col = bn + wn * 64 + nt * 8 + c0;
            float b0 = 0.f, b1 = 0.f;
            if (bias) { b0 = bias[col]; b1 = bias[col + 1]; }
            if (C16) {
                *(__half2*)&C16[(size_t)row * Nc + col] =
                    __floats2half2_rn(acc[mt][nt][0] + b0, acc[mt][nt][1] + b1);
                *(__half2*)&C16[(size_t)(row + 8) * Nc + col] =
                    __floats2half2_rn(acc[mt][nt][2] + b0, acc[mt][nt][3] + b1);
            } else {
                float2 v0, v1;
                v0.x = acc[mt][nt][0] + b0; v0.y = acc[mt][nt][1] + b1;
                v1.x = acc[mt][nt][2] + b0; v1.y = acc[mt][nt][3] + b1;
                *(float2*)&C[(size_t)row * Nc + col]       = v0;
                *(float2*)&C[(size_t)(row + 8) * Nc + col] = v1;
            }
        }
    }
}

// ---------------- gather half 1: hsum tiles (h f32 table) ------------------
__global__ __launch_bounds__(256)
void gather_hsum(const int* __restrict__ idx, const float* __restrict__ h_prev)
{
    const int nb = blockIdx.x * 8;
    const int t  = threadIdx.x;
    const int ln = t >> 5;
    const int n  = nb + ln;
    const int d8 = (t & 31) * 8;

    __shared__ int sidx[8][KC];
    if (t < 128) sidx[t >> 4][t & 15] = idx[(nb + (t >> 4)) * KC + (t & 15)];
    __syncthreads();

    float hs[8] = {0,0,0,0,0,0,0,0};
    if (h_prev) {
#pragma unroll
        for (int k = 0; k < KC; k++) {
            int j = sidx[ln][k];
            if (j >= 1) {
                size_t r = (size_t)(j - 1) * DD + d8;
                float4 h0 = *(const float4*)&h_prev[r];
                float4 h1 = *(const float4*)&h_prev[r + 4];
                hs[0] += h0.x; hs[1] += h0.y; hs[2] += h0.z; hs[3] += h0.w;
                hs[4] += h1.x; hs[5] += h1.y; hs[6] += h1.z; hs[7] += h1.w;
            }
        }
    }
    uint32_t hh[4], ll[4];
#pragma unroll
    for (int q = 0; q < 4; q++) {
        __nv_bfloat162 h, l;
        h.x = __float2bfloat16(hs[q*2+0]);
        h.y = __float2bfloat16(hs[q*2+1]);
        l.x = __float2bfloat16(hs[q*2+0] - __bfloat162float(h.x));
        l.y = __float2bfloat16(hs[q*2+1] - __bfloat162float(h.y));
        hh[q] = *(uint32_t*)&h; ll[q] = *(uint32_t*)&l;
    }
    size_t tile = (size_t)(n >> 7) * 8 + (d8 >> 5);
    unsigned off = SW64((unsigned)((n & 127) * 64 + (d8 & 31) * 2));
    *(uint4*)(g_Ahshi + tile * TILE32 + off) = make_uint4(hh[0], hh[1], hh[2], hh[3]);
    *(uint4*)(g_Ahslo + tile * TILE32 + off) = make_uint4(ll[0], ll[1], ll[2], ll[3]);
}

// ---------------- gather half 2: f (c f32, Hu/Wf fp16) ---------------------
__global__ __launch_bounds__(256)
void gather_f(const int* __restrict__ idx, int have,
              const float* __restrict__ c_prev,
              const __half* __restrict__ Hu,
              const __half* __restrict__ Wf)
{
    const int nb = blockIdx.x * 8;
    const int t  = threadIdx.x;
    const int ln = t >> 5;
    const int n  = nb + ln;
    const int d8 = (t & 31) * 8;

    __shared__ int sidx[8][KC];
    if (t < 128) sidx[t >> 4][t & 15] = idx[(nb + (t >> 4)) * KC + (t & 15)];
    __syncthreads();

    float fs[8] = {0,0,0,0,0,0,0,0};
    if (have) {
        uint4 wraw = *(const uint4*)&Wf[(size_t)n * DD + d8];
        const __half2* w2 = (const __half2*)&wraw;
        float wf[8];
#pragma unroll
        for (int q = 0; q < 4; q++) {
            float2 tv = __half22float2(w2[q]);
            wf[q*2] = tv.x; wf[q*2+1] = tv.y;
        }
#pragma unroll
        for (int k = 0; k < KC; k++) {
            int j = sidx[ln][k];
            if (j >= 1) {
                size_t r = (size_t)(j - 1) * DD + d8;
                uint4 uraw = *(const uint4*)&Hu[r];
                const __half2* u2 = (const __half2*)&uraw;
                float4 c0 = *(const float4*)&c_prev[r];
                float4 c1 = *(const float4*)&c_prev[r + 4];
                const float cv[8] = {c0.x, c0.y, c0.z, c0.w, c1.x, c1.y, c1.z, c1.w};
                float uv[8];
#pragma unroll
                for (int q = 0; q < 4; q++) {
                    float2 tv = __half22float2(u2[q]);
                    uv[q*2] = tv.x; uv[q*2+1] = tv.y;
                }
#pragma unroll
                for (int q = 0; q < 8; q++)
                    fs[q] += sigmoid_fast(wf[q] + uv[q]) * cv[q];
            }
        }
    }
    *(float4*)&g_f[(size_t)n * DD + d8]     = make_float4(fs[0], fs[1], fs[2], fs[3]);
    *(float4*)&g_f[(size_t)n * DD + d8 + 4] = make_float4(fs[4], fs[5], fs[6], fs[7]);
}

// ---------------- gates: 4 dims/thread, HW-exp transcendentals --------------
__global__ __launch_bounds__(256)
void gates_kernel(const float* __restrict__ iuo, const float* __restrict__ f,
                  float* __restrict__ out_h, float* __restrict__ out_c)
{
    const int t  = blockIdx.x * blockDim.x + threadIdx.x;
    const int n  = t >> 6;
    const int d4 = (t & 63) * 4;

    const float* iu = &iuo[(size_t)n * D3];
    float4 vi = *(const float4*)&iu[d4];
    float4 vu = *(const float4*)&iu[DD + d4];
    float4 vo = *(const float4*)&iu[2 * DD + d4];
    float4 ff = *(const float4*)&f[(size_t)n * DD + d4];

    float cc[4], hh[4];
    const float iv[4] = {vi.x, vi.y, vi.z, vi.w};
    const float uv[4] = {vu.x, vu.y, vu.z, vu.w};
    const float ov[4] = {vo.x, vo.y, vo.z, vo.w};
    const float fv[4] = {ff.x, ff.y, ff.z, ff.w};
#pragma unroll
    for (int q = 0; q < 4; q++) {
        cc[q] = sigmoid_hw(iv[q]) * tanh_hw(uv[q]) + fv[q];
        hh[q] = sigmoid_hw(ov[q]) * tanh_hw(cc[q]);
    }
    *(float4*)&out_c[(size_t)n * DD + d4] = make_float4(cc[0], cc[1], cc[2], cc[3]);
    *(float4*)&out_h[(size_t)n * DD + d4] = make_float4(hh[0], hh[1], hh[2], hh[3]);

    __nv_bfloat162 hb0, hb1, lb0, lb1;
    hb0.x = __float2bfloat16(hh[0]); hb0.y = __float2bfloat16(hh[1]);
    hb1.x = __float2bfloat16(hh[2]); hb1.y = __float2bfloat16(hh[3]);
    lb0.x = __float2bfloat16(hh[0] - __bfloat162float(hb0.x));
    lb0.y = __float2bfloat16(hh[1] - __bfloat162float(hb0.y));
    lb1.x = __float2bfloat16(hh[2] - __bfloat162float(hb1.x));
    lb1.y = __float2bfloat16(hh[3] - __bfloat162float(hb1.y));
    size_t tile = (size_t)(n >> 7) * 8 + (d4 >> 5);
    unsigned off = SW64((unsigned)((n & 127) * 64 + (d4 & 31) * 2));
    uint2 hv2, lv2;
    hv2.x = *(uint32_t*)&hb0; hv2.y = *(uint32_t*)&hb1;
    lv2.x = *(uint32_t*)&lb0; lv2.y = *(uint32_t*)&lb1;
    *(uint2*)(g_Ahhi + tile * TILE32 + off) = hv2;
    *(uint2*)(g_Ahlo + tile * TILE32 + off) = lv2;
}

// ---------------- launch -----------------------------------------------------
extern "C" void kernel_launch(void* const* d_in, const int* in_sizes, int n_in,
                              void* d_out, int out_size)
{
    const float* tensor  = (const float*)d_in[0];
    const int*   indices = (const int*)  d_in[1];
    const float* W_w     = (const float*)d_in[2];
    const float* W_b     = (const float*)d_in[3];
    const float* U_f     = (const float*)d_in[4];
    const float* U_iuo   = (const float*)d_in[5];

    float* out_h = (float*)d_out;
    float* out_c = out_h + (size_t)LL * NN * DD;

    __half *wf16, *hu16;
    float *fbuf, *iuo;
    cudaGetSymbolAddress((void**)&wf16, g_Wf16);
    cudaGetSymbolAddress((void**)&hu16, g_Hu16);
    cudaGetSymbolAddress((void**)&fbuf, g_f);
    cudaGetSymbolAddress((void**)&iuo,  g_iuo);
    unsigned char *axhi, *axlo, *ahshi, *ahslo, *ahhi, *ahlo;
    cudaGetSymbolAddress((void**)&axhi,  g_Axhi);
    cudaGetSymbolAddress((void**)&axlo,  g_Axlo);
    cudaGetSymbolAddress((void**)&ahshi, g_Ahshi);
    cudaGetSymbolAddress((void**)&ahslo, g_Ahslo);
    cudaGetSymbolAddress((void**)&ahhi,  g_Ahhi);
    cudaGetSymbolAddress((void**)&ahlo,  g_Ahlo);

    const int SMEM_DYN = 3 * (int)STG;   // 96KB -> 2 CTAs/SM
    cudaFuncSetAttribute(gemm_mma, cudaFuncAttributeMaxDynamicSharedMemorySize, SMEM_DYN);

    const dim3 blk(256);
    const size_t LVL_TILES = (size_t)(NN / 128) * 8 * TILE32;

    // side stream for gather overlap (created per call; intentionally leaked —
    // host-side object only, kernel_launch is invoked a handful of times)
    cudaStream_t s1;
    cudaStreamCreateWithFlags(&s1, cudaStreamNonBlocking);

    // one-time prep (main stream)
    prep_small<<<(256 * 256) / 256, blk>>>(W_w, U_f);
    prep_ext<<<(512 * 768 + 255) / 256, blk>>>(W_w, U_iuo);
    xconv_kernel<<<(NTOT * 64) / 256, blk>>>(tensor);

    // batched Wf = x @ W_f + b_f for levels 1..7 (fp16 out)
    gemm_mma<<<dim3(2, 7 * NN / 128), blk, SMEM_DYN>>>(
        axhi + LVL_TILES, axlo + LVL_TILES, axhi, axlo, 8, 0,
        W_b, nullptr, wf16 + (size_t)NN * DD, DD);

    for (int l = 0; l < LL; l++) {
        const int*   idx = indices + (size_t)l * NN * KC;
        const float* hp  = (l == 0) ? nullptr : out_h + (size_t)(l - 1) * NN * DD;
        const float* cp  = (l == 0) ? nullptr : out_c + (size_t)(l - 1) * NN * DD;

        if (l == 0) {
            // serial: zero hsum tiles + zero f, then iuo + gates
            gather_hsum<<<NN / 8, blk>>>(idx, nullptr);
            gather_f<<<NN / 8, blk>>>(idx, 0, nullptr, hu16, wf16);
            gemm_mma<<<dim3(6, NN / 128), blk, SMEM_DYN>>>(
                ahshi, ahslo, axhi, axlo, 16, 32, W_b + 256, iuo, nullptr, D3);
            gates_kernel<<<(NN * DD / 4) / 256, blk>>>(iuo, fbuf, out_h, out_c);
        } else {
            cudaEvent_t eF, eHs, eHu, eG;
            cudaEventCreateWithFlags(&eF,  cudaEventDisableTiming);
            cudaEventCreateWithFlags(&eHs, cudaEventDisableTiming);
            cudaEventCreateWithFlags(&eHu, cudaEventDisableTiming);
            cudaEventCreateWithFlags(&eG,  cudaEventDisableTiming);

            // fork after gates(l-1): side stream does gather halves
            cudaEventRecord(eF, 0);
            cudaStreamWaitEvent(s1, eF, 0);
            gather_hsum<<<NN / 8, blk, 0, s1>>>(idx, hp);
            cudaEventRecord(eHs, s1);

            // main: Hu = h_prev @ U_f (fp16 out)
            gemm_mma<<<dim3(2, NN / 128), blk, SMEM_DYN>>>(
                ahhi, ahlo, ahhi, ahlo, 8, 16, nullptr, nullptr, hu16, DD);
            cudaEventRecord(eHu, 0);

            // side: gather_f (needs Hu)
            cudaStreamWaitEvent(s1, eHu, 0);
            gather_f<<<NN / 8, blk, 0, s1>>>(idx, 1, cp, hu16,
                                             wf16 + (size_t)l * NN * DD);
            cudaEventRecord(eG, s1);

            // main: iuo GEMM (needs hsum tiles)
            cudaStreamWaitEvent(0, eHs, 0);
            gemm_mma<<<dim3(6, NN / 128), blk, SMEM_DYN>>>(
                ahshi, ahslo,
                axhi + (size_t)l * LVL_TILES,
                axlo + (size_t)l * LVL_TILES,
                16, 32, W_b + 256, iuo, nullptr, D3);

            // main: gates (needs iuo + f)
            cudaStreamWaitEvent(0, eG, 0);
            gates_kernel<<<(NN * DD / 4) / 256, blk>>>(iuo, fbuf,
                                                       out_h + (size_t)l * NN * DD,
                                                       out_c + (size_t)l * NN * DD);
        }
    }
}

// round 17
// speedup vs baseline: 1.5330x; 1.5330x over previous
#include <cuda_runtime.h>
#include <cuda_bf16.h>
#include <cuda_fp16.h>
#include <cstdint>
#include <math.h>

#define LL   8
#define NN   16384
#define KC   16
#define DD   256
#define D4   (4*DD)
#define D3   (3*DD)
#define NTOT (LL*NN)            // 131072

#define SW64(o) ((o) ^ (((o) >> 3) & 0x30))
#define TILE32 8192             // one 128x32 16-bit tile (64B rows, SW64)
#define STG 32768u              // gemm_mma stage: Ahi|Alo|Bhi|Blo x 8KB
#define STGH 24576u             // gemm_hu stage: A|Bhi|Blo x 8KB

__device__ __forceinline__ uint32_t smem_u32(const void* p) {
    uint32_t a;
    asm("{ .reg .u64 t; cvta.to.shared.u64 t, %1; cvt.u32.u64 %0, t; }" : "=r"(a) : "l"(p));
    return a;
}
__device__ __forceinline__ void ldsm_x4(uint32_t& r0, uint32_t& r1, uint32_t& r2,
                                        uint32_t& r3, uint32_t addr) {
    asm volatile("ldmatrix.sync.aligned.m8n8.x4.shared.b16 {%0,%1,%2,%3}, [%4];"
                 : "=r"(r0), "=r"(r1), "=r"(r2), "=r"(r3) : "r"(addr));
}
__device__ __forceinline__ void mma16816(float* c, const uint32_t* a, const uint32_t* b) {
    asm volatile("mma.sync.aligned.m16n8k16.row.col.f32.bf16.bf16.f32 "
                 "{%0,%1,%2,%3}, {%4,%5,%6,%7}, {%8,%9}, {%0,%1,%2,%3};"
                 : "+f"(c[0]), "+f"(c[1]), "+f"(c[2]), "+f"(c[3])
                 : "r"(a[0]), "r"(a[1]), "r"(a[2]), "r"(a[3]), "r"(b[0]), "r"(b[1]));
}
__device__ __forceinline__ void mma16816h(float* c, const uint32_t* a, const uint32_t* b) {
    asm volatile("mma.sync.aligned.m16n8k16.row.col.f32.f16.f16.f32 "
                 "{%0,%1,%2,%3}, {%4,%5,%6,%7}, {%8,%9}, {%0,%1,%2,%3};"
                 : "+f"(c[0]), "+f"(c[1]), "+f"(c[2]), "+f"(c[3])
                 : "r"(a[0]), "r"(a[1]), "r"(a[2]), "r"(a[3]), "r"(b[0]), "r"(b[1]));
}
__device__ __forceinline__ float sigmoid_fast(float z) {
    float t;
    asm("tanh.approx.f32 %0, %1;" : "=f"(t) : "f"(0.5f * z));
    return fmaf(0.5f, t, 0.5f);
}
__device__ __forceinline__ float sigmoid_hw(float z) {
    return 1.f / (1.f + __expf(-z));
}
__device__ __forceinline__ float tanh_hw(float z) {
    return 1.f - 2.f / (__expf(2.f * z) + 1.f);
}
#define CP_ASYNC16(dst, src) \
    asm volatile("cp.async.cg.shared.global [%0], [%1], 16;" :: "r"(dst), "l"(src))
#define CP_COMMIT asm volatile("cp.async.commit_group;" ::: "memory")
#define CP_WAIT2  asm volatile("cp.async.wait_group 2;" ::: "memory")
#define CP_WAIT1  asm volatile("cp.async.wait_group 1;" ::: "memory")
#define CP_WAIT0  asm volatile("cp.async.wait_group 0;" ::: "memory")

// ---------------- scratch (device globals) ---------------------------------
__device__ __half g_Wf16[NTOT * DD];   // fp16 (pre-activation, non-recurrent)
__device__ __half g_Hu16[NN * DD];     // fp16 (pre-activation, non-recurrent)
__device__ float  g_f   [NN * DD];
__device__ float  g_iuo [NN * D3];
// x tiles: bf16 hi/lo (feed 3-pass iuo + Wf GEMMs)
__device__ __align__(1024) unsigned char g_Axhi[NTOT/128 * 8 * TILE32];
__device__ __align__(1024) unsigned char g_Axlo[NTOT/128 * 8 * TILE32];
// hsum tiles: bf16 hi/lo (feed 3-pass iuo GEMM)
__device__ __align__(1024) unsigned char g_Ahshi[NN/128 * 8 * TILE32];
__device__ __align__(1024) unsigned char g_Ahslo[NN/128 * 8 * TILE32];
// h tiles: SINGLE fp16 (feed 2-pass Hu GEMM; forget-path error class)
__device__ __align__(1024) unsigned char g_Ah16[NN/128 * 8 * TILE32];
// B tiles: Wf bf16: 0..15 | U_f fp16 hi(g_Bhi)/lo(g_Blo): 16..31 | B_ext bf16: 32..127
__device__ __align__(1024) unsigned char g_Bhi[128 * TILE32];
__device__ __align__(1024) unsigned char g_Blo[128 * TILE32];

// ---------------- weight prep ----------------------------------------------
__device__ __forceinline__ void put_b(unsigned tile, int n_loc, int k_loc, float v) {
    __nv_bfloat16 hi = __float2bfloat16(v);
    __nv_bfloat16 lo = __float2bfloat16(v - __bfloat162float(hi));
    unsigned off = tile * TILE32 + SW64((unsigned)(n_loc * 64 + k_loc * 2));
    *(__nv_bfloat16*)(g_Bhi + off) = hi;
    *(__nv_bfloat16*)(g_Blo + off) = lo;
}
__device__ __forceinline__ void put_b16(unsigned tile, int n_loc, int k_loc, float v) {
    __half hi = __float2half_rn(v);
    __half lo = __float2half_rn(v - __half2float(hi));
    unsigned off = tile * TILE32 + SW64((unsigned)(n_loc * 64 + k_loc * 2));
    *(__half*)(g_Bhi + off) = hi;
    *(__half*)(g_Blo + off) = lo;
}
__global__ __launch_bounds__(256)
void prep_small(const float* __restrict__ W_w, const float* __restrict__ U_f)
{
    int idx = blockIdx.x * blockDim.x + threadIdx.x;
    int n = idx & 255, k = idx >> 8;
    put_b  ( 0 + (n >> 7) * 8 + (k >> 5), n & 127, k & 31, W_w[k * 1024 + n]);
    put_b16(16 + (n >> 7) * 8 + (k >> 5), n & 127, k & 31, U_f[k * 256 + n]);
}
__global__ __launch_bounds__(256)
void prep_ext(const float* __restrict__ W_w, const float* __restrict__ U_iuo)
{
    int idx = blockIdx.x * blockDim.x + threadIdx.x;
    if (idx >= 512 * 768) return;
    int n = idx % 768, k = idx / 768;
    float v = (k < 256) ? U_iuo[k * 768 + n] : W_w[(k - 256) * 1024 + 256 + n];
    put_b(32 + (n >> 7) * 16 + (k >> 5), n & 127, k & 31, v);
}

// ---------------- x -> bf16 hi/lo tiles -------------------------------------
__global__ __launch_bounds__(256)
void xconv_kernel(const float* __restrict__ x)
{
    int t = blockIdx.x * blockDim.x + threadIdx.x;
    int n = t >> 6, c4 = t & 63;
    float4 v = *(const float4*)&x[(size_t)t * 4];
    __nv_bfloat162 h0, h1, l0, l1;
    h0.x = __float2bfloat16(v.x); h0.y = __float2bfloat16(v.y);
    h1.x = __float2bfloat16(v.z); h1.y = __float2bfloat16(v.w);
    l0.x = __float2bfloat16(v.x - __bfloat162float(h0.x));
    l0.y = __float2bfloat16(v.y - __bfloat162float(h0.y));
    l1.x = __float2bfloat16(v.z - __bfloat162float(h1.x));
    l1.y = __float2bfloat16(v.w - __bfloat162float(h1.y));
    size_t tile = (size_t)(n >> 7) * 8 + (c4 >> 3);
    unsigned off = SW64((unsigned)((n & 127) * 64 + (c4 & 7) * 8));
    uint2 hh, ll;
    hh.x = *(uint32_t*)&h0; hh.y = *(uint32_t*)&h1;
    ll.x = *(uint32_t*)&l0; ll.y = *(uint32_t*)&l1;
    *(uint2*)(g_Axhi + tile * TILE32 + off) = hh;
    *(uint2*)(g_Axlo + tile * TILE32 + off) = ll;
}

// ---------------- 3-pass bf16 GEMM (Wf / iuo), 128x128 tile, 3-stage --------
__global__ __launch_bounds__(256, 2)
void gemm_mma(const unsigned char* __restrict__ A0h, const unsigned char* __restrict__ A0l,
              const unsigned char* __restrict__ A1h, const unsigned char* __restrict__ A1l,
              int kchunks, int btile_base, int btile_stride, int btile_off,
              const float* __restrict__ bias,
              float* __restrict__ C, __half* __restrict__ C16, int Nc)
{
    extern __shared__ char smem[];
    const uint32_t sb = smem_u32(smem);
    const int tid = threadIdx.x, wid = tid >> 5, lane = tid & 31;
    const int wm = wid & 3, wn = wid >> 2;
    const int mb = blockIdx.y, bn = blockIdx.x * 128;

    float acc[2][8][4];
#pragma unroll
    for (int i = 0; i < 2; i++)
#pragma unroll
        for (int j = 0; j < 8; j++)
#pragma unroll
            for (int q = 0; q < 4; q++) acc[i][j][q] = 0.f;

    const int a_row16 = (lane & 7) + ((lane >> 3) & 1) * 8;
    const int a_kb    = (lane >> 4) * 16;
    const int b_row16 = (lane & 7) + ((lane >> 4) << 3);
    const int b_kb    = ((lane >> 3) & 1) * 16;

    uint32_t aRow[2], aXor[2], bRow[4], bXor[4];
#pragma unroll
    for (int mt = 0; mt < 2; mt++) {
        uint32_t r = (uint32_t)(wm * 32 + mt * 16 + a_row16);
        aRow[mt] = r * 64u; aXor[mt] = (r & 6) * 8u;
    }
#pragma unroll
    for (int np = 0; np < 4; np++) {
        uint32_t r = (uint32_t)(wn * 64 + np * 16 + b_row16);
        bRow[np] = 16384u + r * 64u; bXor[np] = (r & 6) * 8u;
    }

    auto load_stage = [&](int stg, int kc) {
        const unsigned char *ah, *al;
        int kcl;
        if (kc < 8) { ah = A0h; al = A0l; kcl = kc; }
        else        { ah = A1h; al = A1l; kcl = kc - 8; }
        size_t at = ((size_t)mb * 8 + kcl) * TILE32;
        size_t bt = (size_t)(btile_base + blockIdx.x * btile_stride + btile_off + kc) * TILE32;
        const unsigned char* srcs[4] = { ah + at, al + at, g_Bhi + bt, g_Blo + bt };
        uint32_t base = sb + (uint32_t)stg * STG;
#pragma unroll
        for (int j = 0; j < 4; j++) {
            uint32_t d = base + j * TILE32 + tid * 16;
            const unsigned char* s = srcs[j] + tid * 16;
            CP_ASYNC16(d, s);
            CP_ASYNC16(d + 4096, s + 4096);
        }
        CP_COMMIT;
    };

    load_stage(0, 0);
    load_stage(1, 1);
    load_stage(2, 2);

    int stg_i = 0;
    for (int kc = 0; kc < kchunks; kc++) {
        if      (kc + 2 < kchunks) CP_WAIT2;
        else if (kc + 1 < kchunks) CP_WAIT1;
        else                       CP_WAIT0;
        __syncthreads();

        const uint32_t stg = sb + (uint32_t)stg_i * STG;
#pragma unroll
        for (int ks = 0; ks < 2; ks++) {
            const uint32_t ka = (uint32_t)(ks * 32 + a_kb);
            const uint32_t kb = (uint32_t)(ks * 32 + b_kb);
            uint32_t av[2][4], bv[4][4];
            // pass 1: A-hi x B-hi
#pragma unroll
            for (int mt = 0; mt < 2; mt++)
                ldsm_x4(av[mt][0], av[mt][1], av[mt][2], av[mt][3],
                        stg + aRow[mt] + (ka ^ aXor[mt]));
#pragma unroll
            for (int np = 0; np < 4; np++)
                ldsm_x4(bv[np][0], bv[np][1], bv[np][2], bv[np][3],
                        stg + bRow[np] + (kb ^ bXor[np]));
#pragma unroll
            for (int mt = 0; mt < 2; mt++)
#pragma unroll
                for (int nt = 0; nt < 8; nt++)
                    mma16816(acc[mt][nt], av[mt], &bv[nt >> 1][(nt & 1) * 2]);
            // pass 2: A-lo x B-hi (reuse B fragments)
#pragma unroll
            for (int mt = 0; mt < 2; mt++)
                ldsm_x4(av[mt][0], av[mt][1], av[mt][2], av[mt][3],
                        stg + TILE32 + aRow[mt] + (ka ^ aXor[mt]));
#pragma unroll
            for (int mt = 0; mt < 2; mt++)
#pragma unroll
                for (int nt = 0; nt < 8; nt++)
                    mma16816(acc[mt][nt], av[mt], &bv[nt >> 1][(nt & 1) * 2]);
            // pass 3: A-hi x B-lo
#pragma unroll
            for (int mt = 0; mt < 2; mt++)
                ldsm_x4(av[mt][0], av[mt][1], av[mt][2], av[mt][3],
                        stg + aRow[mt] + (ka ^ aXor[mt]));
#pragma unroll
            for (int np = 0; np < 4; np++)
                ldsm_x4(bv[np][0], bv[np][1], bv[np][2], bv[np][3],
                        stg + TILE32 + bRow[np] + (kb ^ bXor[np]));
#pragma unroll
            for (int mt = 0; mt < 2; mt++)
#pragma unroll
                for (int nt = 0; nt < 8; nt++)
                    mma16816(acc[mt][nt], av[mt], &bv[nt >> 1][(nt & 1) * 2]);
        }
        __syncthreads();
        if (kc + 3 < kchunks) load_stage(stg_i, kc + 3);
        stg_i = (stg_i == 2) ? 0 : stg_i + 1;
    }

    // epilogue
    const int r0 = lane >> 2, c0 = (lane & 3) * 2;
    const int bm = mb * 128;
#pragma unroll
    for (int mt = 0; mt < 2; mt++) {
#pragma unroll
        for (int nt = 0; nt < 8; nt++) {
            int row = bm + wm * 32 + mt * 16 + r0;
            int col = bn + wn * 64 + nt * 8 + c0;
            float b0 = 0.f, b1 = 0.f;
            if (bias) { b0 = bias[col]; b1 = bias[col + 1]; }
            if (C16) {
                *(__half2*)&C16[(size_t)row * Nc + col] =
                    __floats2half2_rn(acc[mt][nt][0] + b0, acc[mt][nt][1] + b1);
                *(__half2*)&C16[(size_t)(row + 8) * Nc + col] =
                    __floats2half2_rn(acc[mt][nt][2] + b0, acc[mt][nt][3] + b1);
            } else {
                float2 v0, v1;
                v0.x = acc[mt][nt][0] + b0; v0.y = acc[mt][nt][1] + b1;
                v1.x = acc[mt][nt][2] + b0; v1.y = acc[mt][nt][3] + b1;
                *(float2*)&C[(size_t)row * Nc + col]       = v0;
                *(float2*)&C[(size_t)(row + 8) * Nc + col] = v1;
            }
        }
    }
}

// ---------------- 2-pass fp16 Hu GEMM: Hu = h16 @ (Uf_hi + Uf_lo) ----------
__global__ __launch_bounds__(256, 2)
void gemm_hu(__half* __restrict__ C16)
{
    extern __shared__ char smem[];   // 3 stages x [A|Bhi|Blo] x 8KB
    const uint32_t sb = smem_u32(smem);
    const int tid = threadIdx.x, wid = tid >> 5, lane = tid & 31;
    const int wm = wid & 3, wn = wid >> 2;
    const int mb = blockIdx.y, bn = blockIdx.x * 128;

    float acc[2][8][4];
#pragma unroll
    for (int i = 0; i < 2; i++)
#pragma unroll
        for (int j = 0; j < 8; j++)
#pragma unroll
            for (int q = 0; q < 4; q++) acc[i][j][q] = 0.f;

    const int a_row16 = (lane & 7) + ((lane >> 3) & 1) * 8;
    const int a_kb    = (lane >> 4) * 16;
    const int b_row16 = (lane & 7) + ((lane >> 4) << 3);
    const int b_kb    = ((lane >> 3) & 1) * 16;

    uint32_t aRow[2], aXor[2], bRow[4], bXor[4];
#pragma unroll
    for (int mt = 0; mt < 2; mt++) {
        uint32_t r = (uint32_t)(wm * 32 + mt * 16 + a_row16);
        aRow[mt] = r * 64u; aXor[mt] = (r & 6) * 8u;
    }
#pragma unroll
    for (int np = 0; np < 4; np++) {
        uint32_t r = (uint32_t)(wn * 64 + np * 16 + b_row16);
        bRow[np] = 8192u + r * 64u; bXor[np] = (r & 6) * 8u;   // Bhi at +8K, Blo +16K
    }

    auto load_stage = [&](int stg, int kc) {
        size_t at = ((size_t)mb * 8 + kc) * TILE32;
        size_t bt = (size_t)(16 + blockIdx.x * 8 + kc) * TILE32;
        const unsigned char* srcs[3] = { g_Ah16 + at, g_Bhi + bt, g_Blo + bt };
        uint32_t base = sb + (uint32_t)stg * STGH;
#pragma unroll
        for (int j = 0; j < 3; j++) {
            uint32_t d = base + j * TILE32 + tid * 16;
            const unsigned char* s = srcs[j] + tid * 16;
            CP_ASYNC16(d, s);
            CP_ASYNC16(d + 4096, s + 4096);
        }
        CP_COMMIT;
    };

    load_stage(0, 0);
    load_stage(1, 1);
    load_stage(2, 2);

    int stg_i = 0;
    for (int kc = 0; kc < 8; kc++) {
        if      (kc + 2 < 8) CP_WAIT2;
        else if (kc + 1 < 8) CP_WAIT1;
        else                 CP_WAIT0;
        __syncthreads();

        const uint32_t stg = sb + (uint32_t)stg_i * STGH;
#pragma unroll
        for (int ks = 0; ks < 2; ks++) {
            const uint32_t ka = (uint32_t)(ks * 32 + a_kb);
            const uint32_t kb = (uint32_t)(ks * 32 + b_kb);
            uint32_t av[2][4], bv[4][4];
            // A frags (reused across both passes)
#pragma unroll
            for (int mt = 0; mt < 2; mt++)
                ldsm_x4(av[mt][0], av[mt][1], av[mt][2], av[mt][3],
                        stg + aRow[mt] + (ka ^ aXor[mt]));
            // pass 1: A x B-hi
#pragma unroll
            for (int np = 0; np < 4; np++)
                ldsm_x4(bv[np][0], bv[np][1], bv[np][2], bv[np][3],
                        stg + bRow[np] + (kb ^ bXor[np]));
#pragma unroll
            for (int mt = 0; mt < 2; mt++)
#pragma unroll
                for (int nt = 0; nt < 8; nt++)
                    mma16816h(acc[mt][nt], av[mt], &bv[nt >> 1][(nt & 1) * 2]);
            // pass 2: A x B-lo
#pragma unroll
            for (int np = 0; np < 4; np++)
                ldsm_x4(bv[np][0], bv[np][1], bv[np][2], bv[np][3],
                        stg + TILE32 + bRow[np] + (kb ^ bXor[np]));
#pragma unroll
            for (int mt = 0; mt < 2; mt++)
#pragma unroll
                for (int nt = 0; nt < 8; nt++)
                    mma16816h(acc[mt][nt], av[mt], &bv[nt >> 1][(nt & 1) * 2]);
        }
        __syncthreads();
        if (kc + 3 < 8) load_stage(stg_i, kc + 3);
        stg_i = (stg_i == 2) ? 0 : stg_i + 1;
    }

    const int r0 = lane >> 2, c0 = (lane & 3) * 2;
    const int bm = mb * 128;
#pragma unroll
    for (int mt = 0; mt < 2; mt++) {
#pragma unroll
        for (int nt = 0; nt < 8; nt++) {
            int row = bm + wm * 32 + mt * 16 + r0;
            int col = bn + wn * 64 + nt * 8 + c0;
            *(__half2*)&C16[(size_t)row * DD + col] =
                __floats2half2_rn(acc[mt][nt][0], acc[mt][nt][1]);
            *(__half2*)&C16[(size_t)(row + 8) * DD + col] =
                __floats2half2_rn(acc[mt][nt][2], acc[mt][nt][3]);
        }
    }
}

// ---------------- gather: 8 nodes/block, 8 dims/thread ---------------------
__global__ __launch_bounds__(256)
void gather_kernel(const int* __restrict__ idx,
                   const float* __restrict__ h_prev,
                   const float* __restrict__ c_prev,
                   const __half* __restrict__ Hu,
                   const __half* __restrict__ Wf,
                   float* __restrict__ f)
{
    const int nb = blockIdx.x * 8;
    const int t  = threadIdx.x;
    const int ln = t >> 5;
    const int n  = nb + ln;
    const int d8 = (t & 31) * 8;

    __shared__ int sidx[8][KC];
    if (t < 128) sidx[t >> 4][t & 15] = idx[(nb + (t >> 4)) * KC + (t & 15)];
    __syncthreads();

    float hs[8] = {0,0,0,0,0,0,0,0};
    float fs[8] = {0,0,0,0,0,0,0,0};
    if (h_prev) {
        uint4 wraw = *(const uint4*)&Wf[(size_t)n * DD + d8];
        const __half2* w2 = (const __half2*)&wraw;
        float wf[8];
#pragma unroll
        for (int q = 0; q < 4; q++) {
            float2 tv = __half22float2(w2[q]);
            wf[q*2] = tv.x; wf[q*2+1] = tv.y;
        }
#pragma unroll
        for (int k = 0; k < KC; k++) {
            int j = sidx[ln][k];
            if (j >= 1) {
                size_t r = (size_t)(j - 1) * DD + d8;
                float4 h0 = *(const float4*)&h_prev[r];
                float4 h1 = *(const float4*)&h_prev[r + 4];
                uint4 uraw = *(const uint4*)&Hu[r];
                const __half2* u2 = (const __half2*)&uraw;
                float4 c0 = *(const float4*)&c_prev[r];
                float4 c1 = *(const float4*)&c_prev[r + 4];
                const float hv[8] = {h0.x, h0.y, h0.z, h0.w, h1.x, h1.y, h1.z, h1.w};
                const float cv[8] = {c0.x, c0.y, c0.z, c0.w, c1.x, c1.y, c1.z, c1.w};
                float uv[8];
#pragma unroll
                for (int q = 0; q < 4; q++) {
                    float2 tv = __half22float2(u2[q]);
                    uv[q*2] = tv.x; uv[q*2+1] = tv.y;
                }
#pragma unroll
                for (int q = 0; q < 8; q++) {
                    hs[q] += hv[q];
                    fs[q] += sigmoid_fast(wf[q] + uv[q]) * cv[q];
                }
            }
        }
    }
    *(float4*)&f[(size_t)n * DD + d8]     = make_float4(fs[0], fs[1], fs[2], fs[3]);
    *(float4*)&f[(size_t)n * DD + d8 + 4] = make_float4(fs[4], fs[5], fs[6], fs[7]);

    uint32_t hh[4], ll[4];
#pragma unroll
    for (int q = 0; q < 4; q++) {
        __nv_bfloat162 h, l;
        h.x = __float2bfloat16(hs[q*2+0]);
        h.y = __float2bfloat16(hs[q*2+1]);
        l.x = __float2bfloat16(hs[q*2+0] - __bfloat162float(h.x));
        l.y = __float2bfloat16(hs[q*2+1] - __bfloat162float(h.y));
        hh[q] = *(uint32_t*)&h; ll[q] = *(uint32_t*)&l;
    }
    size_t tile = (size_t)(n >> 7) * 8 + (d8 >> 5);
    unsigned off = SW64((unsigned)((n & 127) * 64 + (d8 & 31) * 2));
    *(uint4*)(g_Ahshi + tile * TILE32 + off) = make_uint4(hh[0], hh[1], hh[2], hh[3]);
    *(uint4*)(g_Ahslo + tile * TILE32 + off) = make_uint4(ll[0], ll[1], ll[2], ll[3]);
}

// ---------------- gates: 4 dims/thread, HW-exp; h-tiles single fp16 --------
__global__ __launch_bounds__(256)
void gates_kernel(const float* __restrict__ iuo, const float* __restrict__ f,
                  float* __restrict__ out_h, float* __restrict__ out_c)
{
    const int t  = blockIdx.x * blockDim.x + threadIdx.x;
    const int n  = t >> 6;
    const int d4 = (t & 63) * 4;

    const float* iu = &iuo[(size_t)n * D3];
    float4 vi = *(const float4*)&iu[d4];
    float4 vu = *(const float4*)&iu[DD + d4];
    float4 vo = *(const float4*)&iu[2 * DD + d4];
    float4 ff = *(const float4*)&f[(size_t)n * DD + d4];

    float cc[4], hh[4];
    const float iv[4] = {vi.x, vi.y, vi.z, vi.w};
    const float uv[4] = {vu.x, vu.y, vu.z, vu.w};
    const float ov[4] = {vo.x, vo.y, vo.z, vo.w};
    const float fv[4] = {ff.x, ff.y, ff.z, ff.w};
#pragma unroll
    for (int q = 0; q < 4; q++) {
        cc[q] = sigmoid_hw(iv[q]) * tanh_hw(uv[q]) + fv[q];
        hh[q] = sigmoid_hw(ov[q]) * tanh_hw(cc[q]);
    }
    *(float4*)&out_c[(size_t)n * DD + d4] = make_float4(cc[0], cc[1], cc[2], cc[3]);
    *(float4*)&out_h[(size_t)n * DD + d4] = make_float4(hh[0], hh[1], hh[2], hh[3]);

    // h -> single fp16 tiles (feeds 2-pass Hu GEMM)
    uint2 hv2;
    hv2.x = *(uint32_t*)&(__half2&)*(__half2[]){__floats2half2_rn(hh[0], hh[1])};
    hv2.y = *(uint32_t*)&(__half2&)*(__half2[]){__floats2half2_rn(hh[2], hh[3])};
    size_t tile = (size_t)(n >> 7) * 8 + (d4 >> 5);
    unsigned off = SW64((unsigned)((n & 127) * 64 + (d4 & 31) * 2));
    *(uint2*)(g_Ah16 + tile * TILE32 + off) = hv2;
}

// ---------------- launch -----------------------------------------------------
extern "C" void kernel_launch(void* const* d_in, const int* in_sizes, int n_in,
                              void* d_out, int out_size)
{
    const float* tensor  = (const float*)d_in[0];
    const int*   indices = (const int*)  d_in[1];
    const float* W_w     = (const float*)d_in[2];
    const float* W_b     = (const float*)d_in[3];
    const float* U_f     = (const float*)d_in[4];
    const float* U_iuo   = (const float*)d_in[5];

    float* out_h = (float*)d_out;
    float* out_c = out_h + (size_t)LL * NN * DD;

    __half *wf16, *hu16;
    float *fbuf, *iuo;
    cudaGetSymbolAddress((void**)&wf16, g_Wf16);
    cudaGetSymbolAddress((void**)&hu16, g_Hu16);
    cudaGetSymbolAddress((void**)&fbuf, g_f);
    cudaGetSymbolAddress((void**)&iuo,  g_iuo);
    unsigned char *axhi, *axlo, *ahshi, *ahslo;
    cudaGetSymbolAddress((void**)&axhi,  g_Axhi);
    cudaGetSymbolAddress((void**)&axlo,  g_Axlo);
    cudaGetSymbolAddress((void**)&ahshi, g_Ahshi);
    cudaGetSymbolAddress((void**)&ahslo, g_Ahslo);

    const int SMEM_DYN  = 3 * (int)STG;    // 96KB -> 2 CTAs/SM
    const int SMEM_HU   = 3 * (int)STGH;   // 72KB -> 2 CTAs/SM
    cudaFuncSetAttribute(gemm_mma, cudaFuncAttributeMaxDynamicSharedMemorySize, SMEM_DYN);
    cudaFuncSetAttribute(gemm_hu,  cudaFuncAttributeMaxDynamicSharedMemorySize, SMEM_HU);

    const dim3 blk(256);
    const size_t LVL_TILES = (size_t)(NN / 128) * 8 * TILE32;

    // one-time prep
    prep_small<<<(256 * 256) / 256, blk>>>(W_w, U_f);
    prep_ext<<<(512 * 768 + 255) / 256, blk>>>(W_w, U_iuo);
    xconv_kernel<<<(NTOT * 64) / 256, blk>>>(tensor);

    // batched Wf = x @ W_f + b_f for levels 1..7 (fp16 out)
    gemm_mma<<<dim3(2, 7 * NN / 128), blk, SMEM_DYN>>>(
        axhi + LVL_TILES, axlo + LVL_TILES, axhi, axlo, 8, 0, 8, 0,
        W_b, nullptr, wf16 + (size_t)NN * DD, DD);

    for (int l = 0; l < LL; l++) {
        const int*   idx = indices + (size_t)l * NN * KC;
        const float* hp  = (l == 0) ? nullptr : out_h + (size_t)(l - 1) * NN * DD;
        const float* cp  = (l == 0) ? nullptr : out_c + (size_t)(l - 1) * NN * DD;

        // Hu = h16 @ U_f (2-pass fp16)
        if (l > 0)
            gemm_hu<<<dim3(2, NN / 128), blk, SMEM_HU>>>(hu16);

        gather_kernel<<<NN / 8, blk>>>(idx, hp, cp, hu16,
                                       wf16 + (size_t)l * NN * DD, fbuf);

        if (l == 0) {
            // hsum = 0: only the x-part of iuo (K chunks 8..15)
            gemm_mma<<<dim3(6, NN / 128), blk, SMEM_DYN>>>(
                axhi, axlo, axhi, axlo, 8, 32, 16, 8,
                W_b + 256, iuo, nullptr, D3);
        } else {
            gemm_mma<<<dim3(6, NN / 128), blk, SMEM_DYN>>>(
                ahshi, ahslo,
                axhi + (size_t)l * LVL_TILES,
                axlo + (size_t)l * LVL_TILES,
                16, 32, 16, 0, W_b + 256, iuo, nullptr, D3);
        }

        gates_kernel<<<(NN * DD / 4) / 256, blk>>>(iuo, fbuf,
                                                   out_h + (size_t)l * NN * DD,
                                                   out_c + (size_t)l * NN * DD);
    }
}